// round 3
// baseline (speedup 1.0000x reference)
#include <cuda_runtime.h>
#include <math.h>

// q = prod_i cos(pi/2 + 2*x_i) = prod_i sin(2*x_i)  (8 factors, sign cancels)
// out[row] = { scale*q, -scale*q }
// 4 rows per thread: 8x LDG.128 front-batched (MLP=8), 2x STG.128.

__device__ __forceinline__ float row_prod(float4 a, float4 b)
{
    return __sinf(2.0f * a.x) * __sinf(2.0f * a.y) *
           __sinf(2.0f * a.z) * __sinf(2.0f * a.w) *
           __sinf(2.0f * b.x) * __sinf(2.0f * b.y) *
           __sinf(2.0f * b.z) * __sinf(2.0f * b.w);
}

__global__ __launch_bounds__(256) void qnn_kernel(
    const float4* __restrict__ x4,    // [B*2] float4 (row = 2 float4)
    const float* __restrict__ scale,  // [1]
    float4* __restrict__ out4,        // [B/2] float4 (2 rows per float4)
    int B)
{
    int t = blockIdx.x * blockDim.x + threadIdx.x;   // thread handles rows [4t, 4t+4)
    int r0 = t * 4;
    if (r0 >= B) return;

    // Front-batch all 8 loads
    float4 a0 = x4[r0 * 2 + 0];
    float4 b0 = x4[r0 * 2 + 1];
    float4 a1 = x4[r0 * 2 + 2];
    float4 b1 = x4[r0 * 2 + 3];
    float4 a2 = x4[r0 * 2 + 4];
    float4 b2 = x4[r0 * 2 + 5];
    float4 a3 = x4[r0 * 2 + 6];
    float4 b3 = x4[r0 * 2 + 7];

    float s = *scale;

    float v0 = s * row_prod(a0, b0);
    float v1 = s * row_prod(a1, b1);
    float v2 = s * row_prod(a2, b2);
    float v3 = s * row_prod(a3, b3);

    // out rows r0..r0+3 -> two float4 stores
    out4[t * 2 + 0] = make_float4(v0, -v0, v1, -v1);
    out4[t * 2 + 1] = make_float4(v2, -v2, v3, -v3);
}

extern "C" void kernel_launch(void* const* d_in, const int* in_sizes, int n_in,
                              void* d_out, int out_size)
{
    const float* x     = (const float*)d_in[0];  // [B, 8] float32
    // d_in[1] = weights (unused)
    const float* scale = (const float*)d_in[2];  // scalar float32

    int B = in_sizes[0] / 8;                     // 4194304, divisible by 4
    int threads = 256;
    int rows_per_block = threads * 4;
    int blocks = (B + rows_per_block - 1) / rows_per_block;

    qnn_kernel<<<blocks, threads>>>((const float4*)x, scale, (float4*)d_out, B);
}

// round 4
// speedup vs baseline: 1.3007x; 1.3007x over previous
#include <cuda_runtime.h>
#include <math.h>

// q(row) = prod_i cos(pi/2 + 2*x_i) = prod_i sin(2*x_i)   (8 factors, sign cancels)
// out[row] = { scale*q, -scale*q }
//
// Warp-cooperative layout:
//   - each warp owns 64 consecutive rows = 128 consecutive float4s of x
//   - 4 fully-coalesced LDG.128 per thread (lane-consecutive -> 4 lines/warp-load)
//   - per-float4 partial product, shfl_xor(1) combines the two halves of a row
//   - smem transpose (64 floats/warp) so each lane emits one coalesced float4
//     covering 2 output rows (STG.128)

__device__ __forceinline__ float prod4(float4 f)
{
    return __sinf(2.0f * f.x) * __sinf(2.0f * f.y) *
           __sinf(2.0f * f.z) * __sinf(2.0f * f.w);
}

__global__ __launch_bounds__(256) void qnn_kernel(
    const float4* __restrict__ x4,    // [B*2] float4
    const float* __restrict__ scale,  // [1]
    float4* __restrict__ out4,        // [B/2] float4
    int B)
{
    __shared__ float srow[8][64];     // per-warp row values

    int warp = threadIdx.x >> 5;
    int lane = threadIdx.x & 31;
    int gw   = blockIdx.x * 8 + warp;       // global warp id; owns rows [gw*64, gw*64+64)
    if (gw * 64 >= B) return;

    size_t xbase = (size_t)gw * 128;        // float4 index

    // 4 coalesced, front-batched 16B loads
    float4 f0 = x4[xbase + lane];
    float4 f1 = x4[xbase + 32 + lane];
    float4 f2 = x4[xbase + 64 + lane];
    float4 f3 = x4[xbase + 96 + lane];

    float s = *scale;

    float p0 = prod4(f0);
    float p1 = prod4(f1);
    float p2 = prod4(f2);
    float p3 = prod4(f3);

    // float4 #(xbase + j) is half (j&1) of local row (j>>1) within this warp's 64 rows
    float v0 = p0 * __shfl_xor_sync(0xffffffffu, p0, 1);   // local rows  0..15 (lane>>1)
    float v1 = p1 * __shfl_xor_sync(0xffffffffu, p1, 1);   // local rows 16..31
    float v2 = p2 * __shfl_xor_sync(0xffffffffu, p2, 1);   // local rows 32..47
    float v3 = p3 * __shfl_xor_sync(0xffffffffu, p3, 1);   // local rows 48..63

    int k = lane >> 1;
    if ((lane & 1) == 0) {
        srow[warp][k]      = v0;
        srow[warp][k + 16] = v1;
        srow[warp][k + 32] = v2;
        srow[warp][k + 48] = v3;
    }
    __syncwarp();

    // lane l picks up local rows 2l, 2l+1 -> one float4 of output
    float2 rv = reinterpret_cast<const float2*>(srow[warp])[lane];
    float a = s * rv.x;
    float b = s * rv.y;

    out4[(size_t)gw * 32 + lane] = make_float4(a, -a, b, -b);
}

extern "C" void kernel_launch(void* const* d_in, const int* in_sizes, int n_in,
                              void* d_out, int out_size)
{
    const float* x     = (const float*)d_in[0];  // [B, 8] float32
    // d_in[1] = weights (unused)
    const float* scale = (const float*)d_in[2];  // scalar float32

    int B = in_sizes[0] / 8;                     // 4194304; divisible by 512
    int rows_per_block = 512;                    // 8 warps * 64 rows
    int blocks = (B + rows_per_block - 1) / rows_per_block;

    qnn_kernel<<<blocks, 256>>>((const float4*)x, scale, (float4*)d_out, B);
}

// round 6
// speedup vs baseline: 1.5249x; 1.1724x over previous
#include <cuda_runtime.h>
#include <math.h>

// q(row) = prod_i cos(pi/2 + 2*x_i) = prod_i sin(2*x_i)   (8 factors, sign cancels)
// out[row] = { scale*q, -scale*q }
//
// Warp owns 128 consecutive rows = 256 consecutive float4s of x:
//   - 8 front-batched, fully coalesced LDG.128 per thread (MLP=8)
//   - per-float4 partial product; shfl_xor(1) merges the two halves of each row
//   - smem transpose (128 floats/warp) -> 2 fully coalesced STG.128 per thread

__device__ __forceinline__ float prod4(float4 f)
{
    return __sinf(2.0f * f.x) * __sinf(2.0f * f.y) *
           __sinf(2.0f * f.z) * __sinf(2.0f * f.w);
}

__global__ __launch_bounds__(256) void qnn_kernel(
    const float4* __restrict__ x4,    // [B*2] float4
    const float* __restrict__ scale,  // [1]
    float4* __restrict__ out4,        // [B/2] float4
    int B)
{
    __shared__ float srow[8][128];    // per-warp row values (4 KB total)

    int warp = threadIdx.x >> 5;
    int lane = threadIdx.x & 31;
    int gw   = blockIdx.x * 8 + warp;       // warp owns rows [gw*128, gw*128+128)
    if (gw * 128 >= B) return;

    size_t xbase = (size_t)gw * 256;        // float4 index

    // 8 coalesced, front-batched 16B streaming loads
    float4 f0 = __ldcs(&x4[xbase +   0 + lane]);
    float4 f1 = __ldcs(&x4[xbase +  32 + lane]);
    float4 f2 = __ldcs(&x4[xbase +  64 + lane]);
    float4 f3 = __ldcs(&x4[xbase +  96 + lane]);
    float4 f4 = __ldcs(&x4[xbase + 128 + lane]);
    float4 f5 = __ldcs(&x4[xbase + 160 + lane]);
    float4 f6 = __ldcs(&x4[xbase + 192 + lane]);
    float4 f7 = __ldcs(&x4[xbase + 224 + lane]);

    float s = *scale;

    float p0 = prod4(f0), p1 = prod4(f1), p2 = prod4(f2), p3 = prod4(f3);
    float p4 = prod4(f4), p5 = prod4(f5), p6 = prod4(f6), p7 = prod4(f7);

    // float4 #(xbase + c*32 + lane) is half (lane&1) of local row c*16 + (lane>>1)
    float v0 = p0 * __shfl_xor_sync(0xffffffffu, p0, 1);
    float v1 = p1 * __shfl_xor_sync(0xffffffffu, p1, 1);
    float v2 = p2 * __shfl_xor_sync(0xffffffffu, p2, 1);
    float v3 = p3 * __shfl_xor_sync(0xffffffffu, p3, 1);
    float v4 = p4 * __shfl_xor_sync(0xffffffffu, p4, 1);
    float v5 = p5 * __shfl_xor_sync(0xffffffffu, p5, 1);
    float v6 = p6 * __shfl_xor_sync(0xffffffffu, p6, 1);
    float v7 = p7 * __shfl_xor_sync(0xffffffffu, p7, 1);

    int k = lane >> 1;
    if ((lane & 1) == 0) {
        srow[warp][k      ] = v0;
        srow[warp][k +  16] = v1;
        srow[warp][k +  32] = v2;
        srow[warp][k +  48] = v3;
        srow[warp][k +  64] = v4;
        srow[warp][k +  80] = v5;
        srow[warp][k +  96] = v6;
        srow[warp][k + 112] = v7;
    }
    __syncwarp();

    // lane l emits rows (2l, 2l+1) and (64+2l, 64+2l+1): two coalesced float4 stores
    const float2* sr2 = reinterpret_cast<const float2*>(srow[warp]);
    float2 ra = sr2[lane];
    float2 rb = sr2[lane + 32];

    float a0 = s * ra.x, a1 = s * ra.y;
    float b0 = s * rb.x, b1 = s * rb.y;

    __stcs(&out4[(size_t)gw * 64 + lane],      make_float4(a0, -a0, a1, -a1));
    __stcs(&out4[(size_t)gw * 64 + 32 + lane], make_float4(b0, -b0, b1, -b1));
}

extern "C" void kernel_launch(void* const* d_in, const int* in_sizes, int n_in,
                              void* d_out, int out_size)
{
    const float* x     = (const float*)d_in[0];  // [B, 8] float32
    // d_in[1] = weights (unused)
    const float* scale = (const float*)d_in[2];  // scalar float32

    int B = in_sizes[0] / 8;                     // 4194304; divisible by 1024
    int rows_per_block = 1024;                   // 8 warps * 128 rows
    int blocks = (B + rows_per_block - 1) / rows_per_block;

    qnn_kernel<<<blocks, 256>>>((const float4*)x, scale, (float4*)d_out, B);
}